// round 11
// baseline (speedup 1.0000x reference)
#include <cuda_runtime.h>
#include <cuda_fp16.h>
#include <math.h>

// ---------------- problem constants ----------------
#define MAX_NODES 50000
#define MAX_EDGES 800000

// fp16-compressed per-node records (channel order): per lane 12 halves = uint4 + uint2 (24B)
__device__ uint4 g_node4[MAX_NODES * 32];
__device__ uint2 g_node2[MAX_NODES * 32];
// per-edge packets: 4 x float4 = {src,dst,s0,s1x | s1y,s1z,S00,S01 | S02,S10,S11,S12 | S20,S21,S22,pad}
__device__ float4 g_epack[MAX_EDGES * 4];

// ---- constants derived from the reference's (non-standard) CG formula ----
#define ALPHA0 0.125f
#define ALPHA1 0.10206207261596575f
#define D0 0.6666666666666666f
#define D1 0.3333333333333333f
#define E0 0.6963106238227914f
#define E1 0.17407765595569785f
#define N1 0.48888007f
#define N2 0.04704256f
#define N3 0.06111001f
#define N4 0.12222002f

#define NPW 4   // nodes per warp in precompute

static __device__ __forceinline__ unsigned pack2(float a, float b) {
    half2 h = __floats2half2_rn(a, b);
    return *reinterpret_cast<unsigned*>(&h);
}
static __device__ __forceinline__ float2 unpack2(unsigned u) {
    half2 h = *reinterpret_cast<half2*>(&u);
    return __half22float2(h);
}

// ---------------- pre-pass: build per-edge packets (idx + sh-derived scalars) ----------------
__global__ void shpack_kernel(const float* __restrict__ sh,
                              const int* __restrict__ eidx,
                              int n_edges) {
    int e = blockIdx.x * blockDim.x + threadIdx.x;
    if (e >= n_edges) return;
    const float* s = sh + (size_t)e * 9;
    float s0 = s[0], s1x = s[1], s1y = s[2], s1z = s[3];
    float q0 = s[4], q1v = s[5], q2 = s[6], q3 = s[7], q4 = s[8];

    float n2q2 = N2 * q2;
    float n1q4 = N1 * q4;
    float n1q0 = N1 * q0;
    float S00 = -(n2q2 + n1q4), S01 = N3 * q1v, S02 = n1q0;
    float S10 = N4 * q1v,       S11 = n2q2,     S12 = N4 * q3;
    float S20 = n1q0,           S21 = N3 * q3,  S22 = n1q4 - n2q2;

    float4* p = g_epack + (size_t)e * 4;
    p[0] = make_float4(__int_as_float(eidx[e]), __int_as_float(eidx[n_edges + e]), s0, s1x);
    p[1] = make_float4(s1y, s1z, S00, S01);
    p[2] = make_float4(S02, S10, S11, S12);
    p[3] = make_float4(S20, S21, S22, 0.f);
}

// ---------------- per-node precompute: 4 nodes/warp, lane = channel ----------------
__global__ void __launch_bounds__(256) precompute_kernel(const float* __restrict__ feat,
                                                         const float* __restrict__ W,
                                                         int n_nodes) {
    __shared__ float Ws[5 * 1024];
    __shared__ float4 xs[8][NPW * 32];

    for (int i = threadIdx.x; i < 5 * 1024; i += blockDim.x) {
        int p = i >> 10;
        float s = (p == 0 || p == 3) ? ALPHA0 : ALPHA1;
        Ws[i] = s * W[i];
    }
    __syncthreads();

    int lane = threadIdx.x & 31;
    int wl   = threadIdx.x >> 5;
    int warp = (blockIdx.x * blockDim.x + threadIdx.x) >> 5;
    int nwarp = (gridDim.x * blockDim.x) >> 5;

    for (int nb = warp * NPW; nb < n_nodes; nb += nwarp * NPW) {
        #pragma unroll
        for (int nn = 0; nn < NPW; nn++) {
            int n = nb + nn;
            float4 v = make_float4(0.f, 0.f, 0.f, 0.f);
            if (n < n_nodes) {
                const float* x = feat + (size_t)n * 128;
                v.x = x[lane];
                v.y = x[32 + 3 * lane];
                v.z = x[33 + 3 * lane];
                v.w = x[34 + 3 * lane];
            }
            xs[wl][nn * 32 + lane] = v;
        }
        __syncwarp();

        float a1[NPW], a2[NPW], b3[NPW][3], b4[NPW][3], b5[NPW][3];
        #pragma unroll
        for (int nn = 0; nn < NPW; nn++) {
            a1[nn] = 0.f; a2[nn] = 0.f;
            #pragma unroll
            for (int k = 0; k < 3; k++) { b3[nn][k] = 0.f; b4[nn][k] = 0.f; b5[nn][k] = 0.f; }
        }

        #pragma unroll 4
        for (int u = 0; u < 32; u++) {
            float w0 = Ws[          u * 32 + lane];
            float w1 = Ws[1024 +    u * 32 + lane];
            float w2 = Ws[2048 +    u * 32 + lane];
            float w3 = Ws[3072 +    u * 32 + lane];
            float w4 = Ws[4096 +    u * 32 + lane];
            #pragma unroll
            for (int nn = 0; nn < NPW; nn++) {
                float4 v = xs[wl][nn * 32 + u];   // broadcast
                a1[nn] = fmaf(v.x, w0, a1[nn]);
                a2[nn] = fmaf(v.x, w1, a2[nn]);
                b3[nn][0] = fmaf(v.y, w2, b3[nn][0]);
                b3[nn][1] = fmaf(v.z, w2, b3[nn][1]);
                b3[nn][2] = fmaf(v.w, w2, b3[nn][2]);
                b4[nn][0] = fmaf(v.y, w3, b4[nn][0]);
                b4[nn][1] = fmaf(v.z, w3, b4[nn][1]);
                b4[nn][2] = fmaf(v.w, w3, b4[nn][2]);
                b5[nn][0] = fmaf(v.y, w4, b5[nn][0]);
                b5[nn][1] = fmaf(v.z, w4, b5[nn][1]);
                b5[nn][2] = fmaf(v.w, w4, b5[nn][2]);
            }
        }

        #pragma unroll
        for (int nn = 0; nn < NPW; nn++) {
            int n = nb + nn;
            if (n >= n_nodes) break;
            float c30 = b3[nn][0] * D0, c31 = b3[nn][1] * D1, c32 = b3[nn][2] * D0;
            float c40 = b4[nn][0] * E0, c41 = b4[nn][1] * E1, c42 = b4[nn][2] * E0;
            uint4 p;
            p.x = pack2(a1[nn], a2[nn]);
            p.y = pack2(c30, c31);
            p.z = pack2(c32, c40);
            p.w = pack2(c41, c42);
            uint2 q;
            q.x = pack2(b5[nn][0], b5[nn][1]);
            q.y = pack2(b5[nn][2], 0.f);
            g_node4[n * 32 + lane] = p;
            g_node2[n * 32 + lane] = q;
        }
        __syncwarp();
    }
}

// ---------------- per-edge: uniform packet load + record gather, SMEM transpose, red.v4 ----------------
__global__ void __launch_bounds__(256) edge_kernel(float* __restrict__ out, int n_edges) {
    __shared__ __align__(16) float buf[8][128];
    int lane  = threadIdx.x & 31;
    int wl    = threadIdx.x >> 5;
    int warp  = (blockIdx.x * blockDim.x + threadIdx.x) >> 5;
    int nwarp = (gridDim.x * blockDim.x) >> 5;
    float* b = buf[wl];

    int e = warp;
    float4 P0, P1, P2, P3;
    if (e < n_edges) {
        const float4* p = g_epack + (size_t)e * 4;
        P0 = p[0]; P1 = p[1]; P2 = p[2]; P3 = p[3];
    }

    while (e < n_edges) {
        int src = __float_as_int(P0.x);
        int dst = __float_as_int(P0.y);

        // issue record gather first (longest latency)
        uint4 rp = g_node4[src * 32 + lane];
        uint2 rq = g_node2[src * 32 + lane];

        // prefetch next edge's packet while the gather is in flight
        int en = e + nwarp;
        float4 Q0, Q1, Q2, Q3;
        if (en < n_edges) {
            const float4* p = g_epack + (size_t)en * 4;
            Q0 = p[0]; Q1 = p[1]; Q2 = p[2]; Q3 = p[3];
        }

        float s0  = P0.z, s1x = P0.w, s1y = P1.x, s1z = P1.y;
        float S00 = P1.z, S01 = P1.w, S02 = P2.x;
        float S10 = P2.y, S11 = P2.z, S12 = P2.w;
        float S20 = P3.x, S21 = P3.y, S22 = P3.z;

        float2 u0 = unpack2(rp.x);   // a1, a2
        float2 u1 = unpack2(rp.y);   // b3x, b3y
        float2 u2 = unpack2(rp.z);   // b3z, b4x
        float2 u3 = unpack2(rp.w);   // b4y, b4z
        float2 u4 = unpack2(rq.x);   // b5x, b5y
        float2 u5 = unpack2(rq.y);   // b5z, -
        float a1 = u0.x, a2 = u0.y;
        float b3x = u1.x, b3y = u1.y, b3z = u2.x;
        float b4x = u2.y, b4y = u3.x, b4z = u3.y;
        float b5x = u4.x, b5y = u4.y, b5z = u5.x;

        // out0: paths (0,0,0) and (1,1,0)
        float m0 = s0 * a1;
        m0 = fmaf(s1x, b4x, m0);
        m0 = fmaf(s1y, b4y, m0);
        m0 = fmaf(s1z, b4z, m0);

        // out1: paths (0,1,1), (1,0,1), (1,2,1)
        float m1x = fmaf(D0 * s1x, a2,
                    fmaf(s0, b3x,
                    fmaf(S00, b5x,
                    fmaf(S01, b5y, S02 * b5z))));
        float m1y = fmaf(D1 * s1y, a2,
                    fmaf(s0, b3y,
                    fmaf(S10, b5x,
                    fmaf(S11, b5y, S12 * b5z))));
        float m1z = fmaf(D0 * s1z, a2,
                    fmaf(s0, b3z,
                    fmaf(S20, b5x,
                    fmaf(S21, b5y, S22 * b5z))));

        // SMEM-staged transpose (conflict-free: stride 3 coprime with 32 banks)
        b[lane]              = m0;
        b[32 + 3 * lane + 0] = m1x;
        b[32 + 3 * lane + 1] = m1y;
        b[32 + 3 * lane + 2] = m1z;
        __syncwarp();
        float4 v4 = *reinterpret_cast<float4*>(b + 4 * lane);
        float* dptr = out + (size_t)dst * 128 + 4 * lane;
        asm volatile("red.global.add.v4.f32 [%0], {%1,%2,%3,%4};"
                     :: "l"(dptr), "f"(v4.x), "f"(v4.y), "f"(v4.z), "f"(v4.w) : "memory");
        __syncwarp();

        e = en; P0 = Q0; P1 = Q1; P2 = Q2; P3 = Q3;
    }
}

// ---------------- launch ----------------
extern "C" void kernel_launch(void* const* d_in, const int* in_sizes, int n_in,
                              void* d_out, int out_size) {
    const float* feat = (const float*)d_in[0];
    const float* sh   = (const float*)d_in[1];
    const int*   eidx = (const int*)d_in[2];
    const float* W    = (const float*)d_in[3];
    int n_nodes = in_sizes[0] / 128;
    int n_edges = in_sizes[2] / 2;

    cudaMemsetAsync(d_out, 0, (size_t)out_size * sizeof(float));

    shpack_kernel<<<(n_edges + 255) / 256, 256>>>(sh, eidx, n_edges);

    int warps_needed = (n_nodes + NPW - 1) / NPW;
    int pre_blocks = (warps_needed + 7) / 8;
    precompute_kernel<<<pre_blocks, 256>>>(feat, W, n_nodes);

    edge_kernel<<<2048, 256>>>((float*)d_out, n_edges);
}